// round 3
// baseline (speedup 1.0000x reference)
#include <cuda_runtime.h>
#include <math.h>

// Problem dims (fixed by the dataset)
#define NBATCH 128
#define NI     2048
#define DI     16
#define NO     32
#define DO     16

#define NCHUNK 64                 // i-chunks (partial-reduction granularity)
#define ICHUNK (NI / NCHUNK)      // 32 i per CTA
#define TI     16                 // i per smem stage tile
#define NPHASE (ICHUNK / TI)      // 2
#define JD     (NO * DO)          // 512

// pass 1 tiling
#define BG1    16
#define NBG1   (NBATCH / BG1)     // 8
// pass 2 tiling (smaller to keep regs < 128)
#define BG2    8
#define NBG2   (NBATCH / BG2)     // 16

// Deterministic partial buffers (no atomics anywhere).
__device__ float g_S0part[(size_t)NCHUNK * NBATCH * JD];   // 16.8 MB
__device__ float g_S1part[(size_t)NCHUNK * NBATCH * JD];   // 16.8 MB
__device__ float g_V0[NBATCH * JD];

// ---------------------------------------------------------------------------
// packed f32x2 helpers (Blackwell fma.rn.f32x2)
// ---------------------------------------------------------------------------
__device__ __forceinline__ unsigned long long pk2(float lo, float hi) {
    unsigned long long r;
    asm("mov.b64 %0, {%1, %2};" : "=l"(r)
        : "r"(__float_as_uint(lo)), "r"(__float_as_uint(hi)));
    return r;
}
__device__ __forceinline__ void unpk2(unsigned long long p, float& lo, float& hi) {
    unsigned int a, b;
    asm("mov.b64 {%0, %1}, %2;" : "=r"(a), "=r"(b) : "l"(p));
    lo = __uint_as_float(a); hi = __uint_as_float(b);
}
__device__ __forceinline__ unsigned long long fma2(unsigned long long a,
                                                   unsigned long long b,
                                                   unsigned long long c) {
    unsigned long long d;
    asm("fma.rn.f32x2 %0, %1, %2, %3;" : "=l"(d) : "l"(a), "l"(b), "l"(c));
    return d;
}

// load W rows d0,d0+1 for (i,j) and pack pairs (w_d0[k], w_d1[k])
__device__ __forceinline__ void load_w_packed(const float* __restrict__ W,
                                              int i, int j, int d0,
                                              unsigned long long (&wp)[16])
{
    const float4* Wp = reinterpret_cast<const float4*>(
        W + (((size_t)i * NO + j) * DO + d0) * DI);
#pragma unroll
    for (int q = 0; q < 4; ++q) {
        float4 a = Wp[q];
        float4 b = Wp[4 + q];
        wp[q*4+0] = pk2(a.x, b.x);
        wp[q*4+1] = pk2(a.y, b.y);
        wp[q*4+2] = pk2(a.z, b.z);
        wp[q*4+3] = pk2(a.w, b.w);
    }
}

// stage X tile duplicated: Xs2[(bb*TI+ii)*16 + k] = (x, x)
template<int BGN>
__device__ __forceinline__ void stage_x_dup(float2* Xs2, const float* __restrict__ X,
                                            int bg, int i0, int t)
{
    const float4* Xg = reinterpret_cast<const float4*>(X);
    const int TOT = BGN * TI * 4;     // float4 count
#pragma unroll
    for (int r = 0; r < TOT / 256; ++r) {
        int e   = t + r * 256;
        int bb  = e >> 6;             // TI*4 = 64 float4 per batch
        int rem = e & 63;
        int ii  = rem >> 2;
        int q   = rem & 3;
        float4 v = Xg[(size_t)(bg*BGN + bb) * (NI*4) + (size_t)(i0 + ii) * 4 + q];
        float2* dst = Xs2 + ((bb * TI + ii) * 16 + q * 4);
        dst[0] = make_float2(v.x, v.x);
        dst[1] = make_float2(v.y, v.y);
        dst[2] = make_float2(v.z, v.z);
        dst[3] = make_float2(v.w, v.w);
    }
}

// ---------------------------------------------------------------------------
// Pass 1: S0part[chunk][b][j][d] = sum_{i in chunk} X_hat[b,i,j,d]
// grid (NBG1, NCHUNK), block 256. thread = (j = t>>3, dpair = t&7)
// ---------------------------------------------------------------------------
__global__ __launch_bounds__(256, 2)
void caps_pass1(const float* __restrict__ X, const float* __restrict__ W)
{
    __shared__ __align__(16) float2 Xs2[BG1 * TI * 16];   // 32 KB

    const int bg    = blockIdx.x;
    const int chunk = blockIdx.y;
    const int t     = threadIdx.x;
    const int j     = t >> 3;
    const int d0    = (t & 7) * 2;

    unsigned long long accp[BG1];
#pragma unroll
    for (int b = 0; b < BG1; ++b) accp[b] = 0ull;

    for (int ph = 0; ph < NPHASE; ++ph) {
        const int i0 = chunk * ICHUNK + ph * TI;
        __syncthreads();
        stage_x_dup<BG1>(Xs2, X, bg, i0, t);
        __syncthreads();

        for (int ii = 0; ii < TI; ++ii) {
            unsigned long long wp[16];
            load_w_packed(W, i0 + ii, j, d0, wp);
#pragma unroll
            for (int b = 0; b < BG1; ++b) {
                const ulonglong2* xv = reinterpret_cast<const ulonglong2*>(
                    Xs2 + (b * TI + ii) * 16);
                unsigned long long a = accp[b];
#pragma unroll
                for (int q = 0; q < 8; ++q) {
                    ulonglong2 x2 = xv[q];
                    a = fma2(wp[2*q+0], x2.x, a);
                    a = fma2(wp[2*q+1], x2.y, a);
                }
                accp[b] = a;
            }
        }
    }

    float2* out = reinterpret_cast<float2*>(g_S0part + (size_t)chunk * NBATCH * JD);
#pragma unroll
    for (int b = 0; b < BG1; ++b) {
        int gb = bg * BG1 + b;
        float lo, hi; unpk2(accp[b], lo, hi);
        out[gb * (JD/2) + j * (DO/2) + (d0 >> 1)] = make_float2(lo, hi);
    }
}

// ---------------------------------------------------------------------------
// Reduce S0 partials + squash -> g_V0.  One thread per (b, j, d) = 65536.
// ---------------------------------------------------------------------------
__global__ void caps_squash_v0()
{
    int t = blockIdx.x * blockDim.x + threadIdx.x;   // 65536 threads
    int d = t & 15, j = (t >> 4) & 31, b = t >> 9;
    size_t idx = (size_t)b * JD + (size_t)j * DO + d;
    float s = 0.f;
#pragma unroll 4
    for (int c = 0; c < NCHUNK; ++c)
        s += g_S0part[(size_t)c * (NBATCH * JD) + idx];
    s *= (1.0f / NO);
    float n2 = s * s;
#pragma unroll
    for (int off = 1; off < 16; off <<= 1)
        n2 += __shfl_xor_sync(0xffffffffu, n2, off);
    float f = sqrtf(n2) / (1.0f + n2);
    g_V0[idx] = s * f;
}

// ---------------------------------------------------------------------------
// Pass 2 (fused): X_hat -> b1 -> softmax_j -> S1 partial accumulate.
// grid (NBG2, NCHUNK), block 256. thread = (j, dpair), BG2=8.
// ---------------------------------------------------------------------------
__global__ __launch_bounds__(256, 2)
void caps_pass2(const float* __restrict__ X, const float* __restrict__ W)
{
    __shared__ __align__(16) float2 Xs2[BG2 * TI * 16];   // 16 KB
    __shared__ float  Csm[BG2 * NO];                      // 1 KB (b1, then c)

    const int bg    = blockIdx.x;
    const int chunk = blockIdx.y;
    const int t     = threadIdx.x;
    const int j     = t >> 3;
    const int d0    = (t & 7) * 2;
    const int wz    = t >> 5;
    const int lane  = t & 31;

    // V0 values for this thread's (j, d-pair) across its BG2 batches
    float2 vreg[BG2];
#pragma unroll
    for (int b = 0; b < BG2; ++b)
        vreg[b] = *reinterpret_cast<const float2*>(
            &g_V0[(size_t)(bg * BG2 + b) * JD + j * DO + d0]);

    unsigned long long s1p[BG2];
#pragma unroll
    for (int b = 0; b < BG2; ++b) s1p[b] = 0ull;

    for (int ph = 0; ph < NPHASE; ++ph) {
        const int i0 = chunk * ICHUNK + ph * TI;
        __syncthreads();
        stage_x_dup<BG2>(Xs2, X, bg, i0, t);
        __syncthreads();

        for (int ii = 0; ii < TI; ++ii) {
            unsigned long long wp[16];
            load_w_packed(W, i0 + ii, j, d0, wp);

            unsigned long long xhp[BG2];
#pragma unroll
            for (int b = 0; b < BG2; ++b) {
                const ulonglong2* xv = reinterpret_cast<const ulonglong2*>(
                    Xs2 + (b * TI + ii) * 16);
                unsigned long long a = 0ull;
#pragma unroll
                for (int q = 0; q < 8; ++q) {
                    ulonglong2 x2 = xv[q];
                    a = fma2(wp[2*q+0], x2.x, a);
                    a = fma2(wp[2*q+1], x2.y, a);
                }
                xhp[b] = a;
            }

            // b1 partial over this thread's d-pair, reduce across 8 dpair lanes
            float p[BG2];
#pragma unroll
            for (int b = 0; b < BG2; ++b) {
                float x0, x1; unpk2(xhp[b], x0, x1);
                p[b] = x0 * vreg[b].x + x1 * vreg[b].y;
            }
#pragma unroll
            for (int off = 1; off < 8; off <<= 1)
#pragma unroll
                for (int b = 0; b < BG2; ++b)
                    p[b] += __shfl_xor_sync(0xffffffffu, p[b], off);

            __syncthreads();                 // prior iteration done reading Csm
            if ((t & 7) == 0) {
#pragma unroll
                for (int b = 0; b < BG2; ++b) Csm[b * NO + j] = p[b];
            }
            __syncthreads();

            // softmax over j: warp wz handles batch row wz (8 warps, BG2=8 rows)
            {
                int b = wz;
                float v = Csm[b * NO + lane];
                float m = v;
#pragma unroll
                for (int off = 16; off; off >>= 1)
                    m = fmaxf(m, __shfl_xor_sync(0xffffffffu, m, off));
                float e = __expf(v - m);
                float ss = e;
#pragma unroll
                for (int off = 16; off; off >>= 1)
                    ss += __shfl_xor_sync(0xffffffffu, ss, off);
                Csm[b * NO + lane] = e / ss;
            }
            __syncthreads();

#pragma unroll
            for (int b = 0; b < BG2; ++b) {
                unsigned long long c2 = pk2(Csm[b * NO + j], Csm[b * NO + j]);
                s1p[b] = fma2(c2, xhp[b], s1p[b]);
            }
        }
    }

    float2* out = reinterpret_cast<float2*>(g_S1part + (size_t)chunk * NBATCH * JD);
#pragma unroll
    for (int b = 0; b < BG2; ++b) {
        int gb = bg * BG2 + b;
        float lo, hi; unpk2(s1p[b], lo, hi);
        out[gb * (JD/2) + j * (DO/2) + (d0 >> 1)] = make_float2(lo, hi);
    }
}

// ---------------------------------------------------------------------------
// Reduce S1 partials + squash -> output. One thread per (b, j, d).
// ---------------------------------------------------------------------------
__global__ void caps_squash_out(float* __restrict__ out)
{
    int t = blockIdx.x * blockDim.x + threadIdx.x;
    int d = t & 15, j = (t >> 4) & 31, b = t >> 9;
    size_t idx = (size_t)b * JD + (size_t)j * DO + d;
    float s = 0.f;
#pragma unroll 4
    for (int c = 0; c < NCHUNK; ++c)
        s += g_S1part[(size_t)c * (NBATCH * JD) + idx];
    float n2 = s * s;
#pragma unroll
    for (int off = 1; off < 16; off <<= 1)
        n2 += __shfl_xor_sync(0xffffffffu, n2, off);
    float f = sqrtf(n2) / (1.0f + n2);
    out[idx] = s * f;
}

// ---------------------------------------------------------------------------
extern "C" void kernel_launch(void* const* d_in, const int* in_sizes, int n_in,
                              void* d_out, int out_size)
{
    const float* X = (const float*)d_in[0];
    const float* W = (const float*)d_in[1];
    // defensive: identify by size (X = 4,194,304 ; W = 16,777,216)
    if (n_in >= 2 && in_sizes[0] == NI * NO * DO * DI && in_sizes[1] == NBATCH * NI * DI) {
        W = (const float*)d_in[0];
        X = (const float*)d_in[1];
    }

    dim3 grid1(NBG1, NCHUNK);  // x fast -> same-chunk CTAs co-resident for W L2 reuse
    dim3 grid2(NBG2, NCHUNK);
    caps_pass1<<<grid1, 256>>>(X, W);
    caps_squash_v0<<<256, 256>>>();
    caps_pass2<<<grid2, 256>>>(X, W);
    caps_squash_out<<<256, 256>>>((float*)d_out);
}

// round 4
// speedup vs baseline: 2.1728x; 2.1728x over previous
#include <cuda_runtime.h>
#include <cuda_fp16.h>
#include <math.h>

// Problem dims (fixed by the dataset)
#define NBATCH 128
#define NI     2048
#define DI     16
#define NO     32
#define DO     16

#define NCHUNK 64                 // i-chunks (partial-reduction granularity)
#define ICHUNK (NI / NCHUNK)      // 32 i per CTA
#define TI     16                 // i per smem stage tile
#define NPHASE (ICHUNK / TI)      // 2
#define JD     (NO * DO)          // 512

// K1 tiling
#define BG1    16
#define NBG1   (NBATCH / BG1)     // 8
// route kernel tiling (regs)
#define BG2    8
#define NBG2   (NBATCH / BG2)     // 16

// Deterministic buffers (no atomics anywhere).
__device__ __half g_Xhat[(size_t)NBATCH * NI * JD];        // 268 MB fp16
__device__ float  g_S0part[(size_t)NCHUNK * NBATCH * JD];  // 16.8 MB
__device__ float  g_S1part[(size_t)NCHUNK * NBATCH * JD];  // 16.8 MB
__device__ float  g_V0[NBATCH * JD];

// ---------------------------------------------------------------------------
// helpers
// ---------------------------------------------------------------------------
__device__ __forceinline__ void load_w_rows(const float* __restrict__ W,
                                            int i, int j, int d0,
                                            float (&w0)[16], float (&w1)[16])
{
    const float4* Wp = reinterpret_cast<const float4*>(
        W + (((size_t)i * NO + j) * DO + d0) * DI);
#pragma unroll
    for (int q = 0; q < 4; ++q) {
        float4 a = Wp[q];
        w0[q*4+0] = a.x; w0[q*4+1] = a.y; w0[q*4+2] = a.z; w0[q*4+3] = a.w;
        float4 b = Wp[4+q];
        w1[q*4+0] = b.x; w1[q*4+1] = b.y; w1[q*4+2] = b.z; w1[q*4+3] = b.w;
    }
}

// stage X[bg*BGN .. +BGN][i0 .. i0+TI][0..15] into smem (float4 per (b,ii,q))
template<int BGN>
__device__ __forceinline__ void stage_x(float4* Xs4, const float* __restrict__ X,
                                        int bg, int i0, int t)
{
    const float4* Xg = reinterpret_cast<const float4*>(X);
    const int TOT = BGN * TI * 4;     // float4 count
#pragma unroll
    for (int r = 0; r < TOT / 256; ++r) {
        int e   = t + r * 256;
        int bb  = e >> 6;             // TI*4 = 64 float4 per batch
        int off = e & 63;
        Xs4[e] = Xg[(size_t)(bg*BGN + bb) * (NI*4) + (size_t)i0 * 4 + off];
    }
}

// ---------------------------------------------------------------------------
// K1: X_hat (fp16, materialized) + S0 partials.
// grid (NBG1, NCHUNK), block 256. thread = (j = t>>3, dpair = t&7)
// ---------------------------------------------------------------------------
__global__ __launch_bounds__(256, 2)
void caps_xhat_s0(const float* __restrict__ X, const float* __restrict__ W)
{
    __shared__ __align__(16) float4 Xs4[BG1 * TI * 4];   // 16 KB

    const int bg    = blockIdx.x;
    const int chunk = blockIdx.y;
    const int t     = threadIdx.x;
    const int j     = t >> 3;
    const int d0    = (t & 7) * 2;

    float acc0[BG1], acc1[BG1];
#pragma unroll
    for (int b = 0; b < BG1; ++b) { acc0[b] = 0.f; acc1[b] = 0.f; }

    for (int ph = 0; ph < NPHASE; ++ph) {
        const int i0 = chunk * ICHUNK + ph * TI;
        __syncthreads();
        stage_x<BG1>(Xs4, X, bg, i0, t);
        __syncthreads();

        for (int ii = 0; ii < TI; ++ii) {
            const int i = i0 + ii;
            float w0[16], w1[16];
            load_w_rows(W, i, j, d0, w0, w1);
#pragma unroll
            for (int b = 0; b < BG1; ++b) {
                float a0 = 0.f, a1 = 0.f;
#pragma unroll
                for (int q = 0; q < 4; ++q) {
                    float4 xv = Xs4[(b * TI + ii) * 4 + q];
                    a0 = fmaf(w0[q*4+0], xv.x, a0); a1 = fmaf(w1[q*4+0], xv.x, a1);
                    a0 = fmaf(w0[q*4+1], xv.y, a0); a1 = fmaf(w1[q*4+1], xv.y, a1);
                    a0 = fmaf(w0[q*4+2], xv.z, a0); a1 = fmaf(w1[q*4+2], xv.z, a1);
                    a0 = fmaf(w0[q*4+3], xv.w, a0); a1 = fmaf(w1[q*4+3], xv.w, a1);
                }
                acc0[b] += a0; acc1[b] += a1;
                size_t off = ((size_t)(bg * BG1 + b) * NI + i) * JD + j * DO + d0;
                *reinterpret_cast<__half2*>(&g_Xhat[off]) = __floats2half2_rn(a0, a1);
            }
        }
    }

    float2* out = reinterpret_cast<float2*>(g_S0part + (size_t)chunk * NBATCH * JD);
#pragma unroll
    for (int b = 0; b < BG1; ++b) {
        int gb = bg * BG1 + b;
        out[gb * (JD/2) + j * (DO/2) + (d0 >> 1)] = make_float2(acc0[b], acc1[b]);
    }
}

// ---------------------------------------------------------------------------
// K2: reduce S0 partials + squash -> g_V0.  One thread per (b, j, d) = 65536.
// ---------------------------------------------------------------------------
__global__ void caps_squash_v0()
{
    int t = blockIdx.x * blockDim.x + threadIdx.x;
    int d = t & 15, j = (t >> 4) & 31, b = t >> 9;
    size_t idx = (size_t)b * JD + (size_t)j * DO + d;
    float s = 0.f;
#pragma unroll 4
    for (int c = 0; c < NCHUNK; ++c)
        s += g_S0part[(size_t)c * (NBATCH * JD) + idx];
    s *= (1.0f / NO);
    float n2 = s * s;
#pragma unroll
    for (int off = 1; off < 16; off <<= 1)
        n2 += __shfl_xor_sync(0xffffffffu, n2, off);
    float f = sqrtf(n2) / (1.0f + n2);
    g_V0[idx] = s * f;
}

// ---------------------------------------------------------------------------
// K3 (route, fused): read X_hat(fp16) -> b1 -> softmax_j -> S1 partials.
// grid (NBG2, NCHUNK), block 256. thread = (j, dpair), BG2=8.
// Memory-bound: streams 268 MB of X_hat; no X_hat recompute.
// ---------------------------------------------------------------------------
__global__ __launch_bounds__(256, 2)
void caps_route_s1(void)
{
    __shared__ float Csm[BG2 * NO];     // 1 KB (b1, then c)

    const int bg    = blockIdx.x;
    const int chunk = blockIdx.y;
    const int t     = threadIdx.x;
    const int j     = t >> 3;
    const int d0    = (t & 7) * 2;
    const int wz    = t >> 5;
    const int lane  = t & 31;

    // V0 values for this thread's (j, d-pair) across its BG2 batches
    float2 vreg[BG2];
#pragma unroll
    for (int b = 0; b < BG2; ++b)
        vreg[b] = *reinterpret_cast<const float2*>(
            &g_V0[(size_t)(bg * BG2 + b) * JD + j * DO + d0]);

    float s1a[BG2], s1b[BG2];
#pragma unroll
    for (int b = 0; b < BG2; ++b) { s1a[b] = 0.f; s1b[b] = 0.f; }

    for (int il = 0; il < ICHUNK; ++il) {
        const int i = chunk * ICHUNK + il;

        // load X_hat pair for all BG2 batches
        float2 xf[BG2];
#pragma unroll
        for (int b = 0; b < BG2; ++b) {
            size_t off = ((size_t)(bg * BG2 + b) * NI + i) * JD + j * DO + d0;
            __half2 h = *reinterpret_cast<const __half2*>(&g_Xhat[off]);
            xf[b] = __half22float2(h);
        }

        // b1 partial over this thread's d-pair, reduce across 8 dpair lanes
        float p[BG2];
#pragma unroll
        for (int b = 0; b < BG2; ++b)
            p[b] = xf[b].x * vreg[b].x + xf[b].y * vreg[b].y;
#pragma unroll
        for (int off = 1; off < 8; off <<= 1)
#pragma unroll
            for (int b = 0; b < BG2; ++b)
                p[b] += __shfl_xor_sync(0xffffffffu, p[b], off);

        __syncthreads();                 // prior iteration done reading Csm
        if ((t & 7) == 0) {
#pragma unroll
            for (int b = 0; b < BG2; ++b) Csm[b * NO + j] = p[b];
        }
        __syncthreads();

        // softmax over j: warp wz handles batch row wz (8 warps, BG2=8 rows)
        {
            int b = wz;
            float v = Csm[b * NO + lane];
            float m = v;
#pragma unroll
            for (int off = 16; off; off >>= 1)
                m = fmaxf(m, __shfl_xor_sync(0xffffffffu, m, off));
            float e = __expf(v - m);
            float ss = e;
#pragma unroll
            for (int off = 16; off; off >>= 1)
                ss += __shfl_xor_sync(0xffffffffu, ss, off);
            Csm[b * NO + lane] = e / ss;
        }
        __syncthreads();

#pragma unroll
        for (int b = 0; b < BG2; ++b) {
            float c = Csm[b * NO + j];
            s1a[b] = fmaf(c, xf[b].x, s1a[b]);
            s1b[b] = fmaf(c, xf[b].y, s1b[b]);
        }
    }

    float2* out = reinterpret_cast<float2*>(g_S1part + (size_t)chunk * NBATCH * JD);
#pragma unroll
    for (int b = 0; b < BG2; ++b) {
        int gb = bg * BG2 + b;
        out[gb * (JD/2) + j * (DO/2) + (d0 >> 1)] = make_float2(s1a[b], s1b[b]);
    }
}

// ---------------------------------------------------------------------------
// K4: reduce S1 partials + squash -> output. One thread per (b, j, d).
// ---------------------------------------------------------------------------
__global__ void caps_squash_out(float* __restrict__ out)
{
    int t = blockIdx.x * blockDim.x + threadIdx.x;
    int d = t & 15, j = (t >> 4) & 31, b = t >> 9;
    size_t idx = (size_t)b * JD + (size_t)j * DO + d;
    float s = 0.f;
#pragma unroll 4
    for (int c = 0; c < NCHUNK; ++c)
        s += g_S1part[(size_t)c * (NBATCH * JD) + idx];
    float n2 = s * s;
#pragma unroll
    for (int off = 1; off < 16; off <<= 1)
        n2 += __shfl_xor_sync(0xffffffffu, n2, off);
    float f = sqrtf(n2) / (1.0f + n2);
    out[idx] = s * f;
}

// ---------------------------------------------------------------------------
extern "C" void kernel_launch(void* const* d_in, const int* in_sizes, int n_in,
                              void* d_out, int out_size)
{
    const float* X = (const float*)d_in[0];
    const float* W = (const float*)d_in[1];
    // defensive: identify by size (X = 4,194,304 ; W = 16,777,216)
    if (n_in >= 2 && in_sizes[0] == NI * NO * DO * DI && in_sizes[1] == NBATCH * NI * DI) {
        W = (const float*)d_in[0];
        X = (const float*)d_in[1];
    }

    dim3 grid1(NBG1, NCHUNK);  // x fast -> same-chunk CTAs co-resident for W L2 reuse
    dim3 grid2(NBG2, NCHUNK);
    caps_xhat_s0<<<grid1, 256>>>(X, W);
    caps_squash_v0<<<256, 256>>>();
    caps_route_s1<<<grid2, 256>>>();
    caps_squash_out<<<256, 256>>>((float*)d_out);
}

// round 5
// speedup vs baseline: 2.3654x; 1.0886x over previous
#include <cuda_runtime.h>
#include <cuda_fp16.h>
#include <math.h>

// Problem dims (fixed by the dataset)
#define NBATCH 128
#define NI     2048
#define DI     16
#define NO     32
#define DO     16
#define JD     (NO * DO)          // 512

// K1 (mma) tiling: CTA = 128 b x 256 n (half of W) x II i's
#define II     8
#define NIB    (NI / II)          // 256 i-blocks
// K3 tiling: warp per (b, i-chunk)
#define WPB    64                 // warps (i-chunks) per batch
#define ICH3   (NI / WPB)         // 32 i per warp
// S1 partial chunks
#define NCH1   WPB                // 64

// Deterministic buffers (no atomics anywhere).
__device__ __half g_Xhat[(size_t)NBATCH * NI * JD];          // 268 MB fp16
__device__ float  g_S0part[(size_t)NIB * NBATCH * JD];       // 67 MB
__device__ float  g_S1part[(size_t)NCH1 * NBATCH * JD];      // 16.8 MB
__device__ float  g_V0[NBATCH * JD];

// ---------------------------------------------------------------------------
// mma.sync m16n8k16 f16 -> f32
// ---------------------------------------------------------------------------
__device__ __forceinline__ void mma16816(float& d0, float& d1, float& d2, float& d3,
                                         unsigned a0, unsigned a1, unsigned a2, unsigned a3,
                                         unsigned b0, unsigned b1)
{
    asm volatile(
        "mma.sync.aligned.m16n8k16.row.col.f32.f16.f16.f32 "
        "{%0,%1,%2,%3}, {%4,%5,%6,%7}, {%8,%9}, {%10,%11,%12,%13};"
        : "=f"(d0), "=f"(d1), "=f"(d2), "=f"(d3)
        : "r"(a0), "r"(a1), "r"(a2), "r"(a3), "r"(b0), "r"(b1),
          "f"(0.0f), "f"(0.0f), "f"(0.0f), "f"(0.0f));
}

__device__ __forceinline__ unsigned pkh2(float x, float y) {
    __half2 h = __floats2half2_rn(x, y);
    return *reinterpret_cast<unsigned*>(&h);
}

// ---------------------------------------------------------------------------
// K1: X_hat (fp16) + S0 partials via tensor cores.
// grid (2 nhalf, NIB), block 256 (8 warps).
// Warp w covers n-local [32w, 32w+32) (4 n-tiles), all 8 m-tiles (128 b).
// S0 accumulates in registers across the CTA's II i's.
// ---------------------------------------------------------------------------
__global__ __launch_bounds__(256, 1)
void caps_xhat_s0_mma(const float* __restrict__ X, const float* __restrict__ W)
{
    __shared__ __align__(16) __half Wsm[256 * 16];   // 8 KB  [nlocal][k]
    __shared__ __align__(16) __half Xsm[128 * 16];   // 4 KB  [b][k]

    const int nhalf = blockIdx.x;
    const int iblk  = blockIdx.y;
    const int t     = threadIdx.x;
    const int w     = t >> 5;
    const int l     = t & 31;
    const int g     = l >> 2;       // fragment group (row)
    const int tq    = l & 3;        // fragment thread-in-group (col pair)
    const int nbase = nhalf * 256;

    unsigned* Wu = reinterpret_cast<unsigned*>(Wsm);
    unsigned* Xu = reinterpret_cast<unsigned*>(Xsm);

    float s0[32][4];                // [mt*4+nt][frag reg]
#pragma unroll
    for (int q = 0; q < 32; ++q) { s0[q][0]=0.f; s0[q][1]=0.f; s0[q][2]=0.f; s0[q][3]=0.f; }

    for (int ii = 0; ii < II; ++ii) {
        const int i = iblk * II + ii;
        __syncthreads();
        // stage W half: 256n x 16k fp32 -> fp16 (1024 float4, 4 per thread)
#pragma unroll
        for (int r = 0; r < 4; ++r) {
            int e  = t + r * 256;
            int nl = e >> 2, k4 = e & 3;
            float4 v = *reinterpret_cast<const float4*>(
                W + ((size_t)i * JD + nbase + nl) * DI + k4 * 4);
            uint2 h; h.x = pkh2(v.x, v.y); h.y = pkh2(v.z, v.w);
            *reinterpret_cast<uint2*>(Wu + nl * 8 + k4 * 2) = h;
        }
        // stage X: 128b x 16k fp32 -> fp16 (512 float4, 2 per thread)
#pragma unroll
        for (int r = 0; r < 2; ++r) {
            int e = t + r * 256;
            int b = e >> 2, k4 = e & 3;
            float4 v = *reinterpret_cast<const float4*>(
                X + ((size_t)b * NI + i) * DI + k4 * 4);
            uint2 h; h.x = pkh2(v.x, v.y); h.y = pkh2(v.z, v.w);
            *reinterpret_cast<uint2*>(Xu + b * 8 + k4 * 2) = h;
        }
        __syncthreads();

        // A fragments: 8 m-tiles
        unsigned a[8][4];
#pragma unroll
        for (int mt = 0; mt < 8; ++mt) {
            int base = (mt * 16 + g) * 8 + tq;   // uint index into Xu
            a[mt][0] = Xu[base];        // (g,      k 2t..2t+1)
            a[mt][1] = Xu[base + 64];   // (g+8,    k 2t..2t+1)
            a[mt][2] = Xu[base + 4];    // (g,      k 2t+8..9)
            a[mt][3] = Xu[base + 68];   // (g+8,    k 2t+8..9)
        }
        // B fragments: this warp's 4 n-tiles
        unsigned bf[4][2];
#pragma unroll
        for (int nt = 0; nt < 4; ++nt) {
            int base = (w * 32 + nt * 8 + g) * 8 + tq;
            bf[nt][0] = Wu[base];       // (k 2t..2t+1,  n g)
            bf[nt][1] = Wu[base + 4];   // (k 2t+8..9,   n g)
        }

#pragma unroll
        for (int nt = 0; nt < 4; ++nt) {
            const int n = nbase + w * 32 + nt * 8 + tq * 2;
#pragma unroll
            for (int mt = 0; mt < 8; ++mt) {
                float d0, d1, d2, d3;
                mma16816(d0, d1, d2, d3,
                         a[mt][0], a[mt][1], a[mt][2], a[mt][3],
                         bf[nt][0], bf[nt][1]);
                float* s = s0[mt * 4 + nt];
                s[0] += d0; s[1] += d1; s[2] += d2; s[3] += d3;
                const int bq = mt * 16 + g;
                __half2 h01 = __floats2half2_rn(d0, d1);
                __half2 h23 = __floats2half2_rn(d2, d3);
                *reinterpret_cast<__half2*>(
                    &g_Xhat[((size_t)bq * NI + i) * JD + n]) = h01;
                *reinterpret_cast<__half2*>(
                    &g_Xhat[((size_t)(bq + 8) * NI + i) * JD + n]) = h23;
            }
        }
    }

    // write S0 partials: [iblk][b][n]
    float* outp = g_S0part + (size_t)iblk * (NBATCH * JD);
#pragma unroll
    for (int nt = 0; nt < 4; ++nt) {
        const int n = nbase + w * 32 + nt * 8 + tq * 2;
#pragma unroll
        for (int mt = 0; mt < 8; ++mt) {
            const float* s = s0[mt * 4 + nt];
            const int bq = mt * 16 + g;
            *reinterpret_cast<float2*>(&outp[(size_t)bq * JD + n])
                = make_float2(s[0], s[1]);
            *reinterpret_cast<float2*>(&outp[(size_t)(bq + 8) * JD + n])
                = make_float2(s[2], s[3]);
        }
    }
}

// ---------------------------------------------------------------------------
// K2: reduce S0 partials + squash -> g_V0.  One thread per (b, j, d) = 65536.
// idx == global thread id (layout matches), fully coalesced.
// ---------------------------------------------------------------------------
__global__ void caps_squash_v0()
{
    int t = blockIdx.x * blockDim.x + threadIdx.x;
    float s = 0.f;
#pragma unroll 4
    for (int c = 0; c < NIB; ++c)
        s += g_S0part[(size_t)c * (NBATCH * JD) + t];
    s *= (1.0f / NO);
    float n2 = s * s;
#pragma unroll
    for (int off = 1; off < 16; off <<= 1)
        n2 += __shfl_xor_sync(0xffffffffu, n2, off);
    float f = sqrtf(n2) / (1.0f + n2);
    g_V0[t] = s * f;
}

// ---------------------------------------------------------------------------
// K3: warp per (b, i-chunk). lane = j. v0 and s1 in registers.
// Streams X_hat once (268 MB), one softmax per (b,i).
// ---------------------------------------------------------------------------
__global__ __launch_bounds__(256, 4)
void caps_route_s1()
{
    const int wid = blockIdx.x * 8 + (threadIdx.x >> 5);  // 0..8191
    const int j   = threadIdx.x & 31;
    const int b   = wid >> 6;          // 0..127
    const int ch  = wid & (WPB - 1);   // 0..63

    // v0[b][j][0..15] into registers
    float v[16];
    {
        const float4* vp = reinterpret_cast<const float4*>(
            &g_V0[((size_t)b * NO + j) * DO]);
#pragma unroll
        for (int q = 0; q < 4; ++q) {
            float4 x = vp[q];
            v[q*4+0] = x.x; v[q*4+1] = x.y; v[q*4+2] = x.z; v[q*4+3] = x.w;
        }
    }

    float s1[16];
#pragma unroll
    for (int d = 0; d < 16; ++d) s1[d] = 0.f;

    for (int iiv = 0; iiv < ICH3; ++iiv) {
        const int i = ch * ICH3 + iiv;
        const uint4* xp = reinterpret_cast<const uint4*>(
            &g_Xhat[((size_t)b * NI + i) * JD + j * DO]);
        uint4 x0 = xp[0], x1 = xp[1];

        float xf[16];
        {
            const unsigned u[8] = {x0.x, x0.y, x0.z, x0.w, x1.x, x1.y, x1.z, x1.w};
#pragma unroll
            for (int q = 0; q < 8; ++q) {
                float2 f2 = __half22float2(*reinterpret_cast<const __half2*>(&u[q]));
                xf[q*2+0] = f2.x; xf[q*2+1] = f2.y;
            }
        }

        // b1 logit for (b, i, j=lane)
        float p = 0.f;
#pragma unroll
        for (int d = 0; d < 16; ++d) p = fmaf(xf[d], v[d], p);

        // softmax over the 32 lanes (j axis)
        float m = p;
#pragma unroll
        for (int off = 16; off; off >>= 1)
            m = fmaxf(m, __shfl_xor_sync(0xffffffffu, m, off));
        float e = __expf(p - m);
        float ss = e;
#pragma unroll
        for (int off = 16; off; off >>= 1)
            ss += __shfl_xor_sync(0xffffffffu, ss, off);
        float c = e / ss;

#pragma unroll
        for (int d = 0; d < 16; ++d) s1[d] = fmaf(c, xf[d], s1[d]);
    }

    // store partials [ch][b][j][d]
    float* o = g_S1part + (((size_t)ch * NBATCH + b) * NO + j) * DO;
#pragma unroll
    for (int q = 0; q < 4; ++q)
        *reinterpret_cast<float4*>(o + q * 4)
            = make_float4(s1[q*4+0], s1[q*4+1], s1[q*4+2], s1[q*4+3]);
}

// ---------------------------------------------------------------------------
// K4: reduce S1 partials + squash -> output. One thread per (b, j, d).
// ---------------------------------------------------------------------------
__global__ void caps_squash_out(float* __restrict__ out)
{
    int t = blockIdx.x * blockDim.x + threadIdx.x;
    float s = 0.f;
#pragma unroll 4
    for (int c = 0; c < NCH1; ++c)
        s += g_S1part[(size_t)c * (NBATCH * JD) + t];
    float n2 = s * s;
#pragma unroll
    for (int off = 1; off < 16; off <<= 1)
        n2 += __shfl_xor_sync(0xffffffffu, n2, off);
    float f = sqrtf(n2) / (1.0f + n2);
    out[t] = s * f;
}

// ---------------------------------------------------------------------------
extern "C" void kernel_launch(void* const* d_in, const int* in_sizes, int n_in,
                              void* d_out, int out_size)
{
    const float* X = (const float*)d_in[0];
    const float* W = (const float*)d_in[1];
    // defensive: identify by size (X = 4,194,304 ; W = 16,777,216)
    if (n_in >= 2 && in_sizes[0] == NI * NO * DO * DI && in_sizes[1] == NBATCH * NI * DI) {
        W = (const float*)d_in[0];
        X = (const float*)d_in[1];
    }

    dim3 grid1(2, NIB);        // 512 CTAs
    caps_xhat_s0_mma<<<grid1, 256>>>(X, W);
    caps_squash_v0<<<256, 256>>>();
    caps_route_s1<<<1024, 256>>>();
    caps_squash_out<<<256, 256>>>((float*)d_out);
}

// round 6
// speedup vs baseline: 2.6527x; 1.1215x over previous
#include <cuda_runtime.h>
#include <cuda_fp16.h>
#include <math.h>

// Problem dims (fixed by the dataset)
#define NBATCH 128
#define NI     2048
#define DI     16
#define NO     32
#define DO     16
#define JD     (NO * DO)          // 512

// K1 (mma) tiling: CTA = 128 b x 128 n (quarter of W) x II i's
#define II     8
#define NIB    (NI / II)          // 256 i-blocks
// K3 tiling: warp per (b, i-chunk)
#define WPB    32                 // warps (i-chunks) per batch
#define ICH3   (NI / WPB)         // 64 i per warp
#define NCH1   WPB                // 32 S1 partial chunks

// Deterministic buffers (no atomics anywhere).
__device__ __half g_Xhat[(size_t)NBATCH * NI * JD];          // 268 MB fp16
__device__ float  g_S0part[(size_t)NIB * NBATCH * JD];       // 67 MB
__device__ float  g_S1part[(size_t)NCH1 * NBATCH * JD];      // 8.4 MB
__device__ float  g_V0[NBATCH * JD];

// ---------------------------------------------------------------------------
// mma.sync m16n8k16 f16 -> f32
// ---------------------------------------------------------------------------
__device__ __forceinline__ void mma16816(float& d0, float& d1, float& d2, float& d3,
                                         unsigned a0, unsigned a1, unsigned a2, unsigned a3,
                                         unsigned b0, unsigned b1)
{
    asm volatile(
        "mma.sync.aligned.m16n8k16.row.col.f32.f16.f16.f32 "
        "{%0,%1,%2,%3}, {%4,%5,%6,%7}, {%8,%9}, {%10,%11,%12,%13};"
        : "=f"(d0), "=f"(d1), "=f"(d2), "=f"(d3)
        : "r"(a0), "r"(a1), "r"(a2), "r"(a3), "r"(b0), "r"(b1),
          "f"(0.0f), "f"(0.0f), "f"(0.0f), "f"(0.0f));
}

__device__ __forceinline__ unsigned pkh2(float x, float y) {
    __half2 h = __floats2half2_rn(x, y);
    return *reinterpret_cast<unsigned*>(&h);
}

// ---------------------------------------------------------------------------
// K1: X_hat (fp16) + S0 partials via tensor cores.
// grid (4 nq, NIB), block 256 (8 warps), 2 CTAs/SM.
// Warp w covers n-local [16w, 16w+16) (2 n-tiles), all 8 m-tiles (128 b).
// ---------------------------------------------------------------------------
__global__ __launch_bounds__(256, 2)
void caps_xhat_s0_mma(const float* __restrict__ X, const float* __restrict__ W)
{
    __shared__ __align__(16) __half Wsm[128 * 16];   // 4 KB  [nlocal][k]
    __shared__ __align__(16) __half Xsm[128 * 16];   // 4 KB  [b][k]

    const int nq    = blockIdx.x;
    const int iblk  = blockIdx.y;
    const int t     = threadIdx.x;
    const int w     = t >> 5;
    const int l     = t & 31;
    const int g     = l >> 2;       // fragment group (row)
    const int tq    = l & 3;        // fragment thread-in-group (col pair)
    const int nbase = nq * 128;

    unsigned* Wu = reinterpret_cast<unsigned*>(Wsm);
    unsigned* Xu = reinterpret_cast<unsigned*>(Xsm);

    float s0[16][4];                // [nt*8+mt][frag reg]
#pragma unroll
    for (int q = 0; q < 16; ++q) { s0[q][0]=0.f; s0[q][1]=0.f; s0[q][2]=0.f; s0[q][3]=0.f; }

    for (int ii = 0; ii < II; ++ii) {
        const int i = iblk * II + ii;
        __syncthreads();
        // stage W quarter: 128n x 16k fp32 -> fp16 (512 float4, 2 per thread)
#pragma unroll
        for (int r = 0; r < 2; ++r) {
            int e  = t + r * 256;
            int nl = e >> 2, k4 = e & 3;
            float4 v = *reinterpret_cast<const float4*>(
                W + ((size_t)i * JD + nbase + nl) * DI + k4 * 4);
            uint2 h; h.x = pkh2(v.x, v.y); h.y = pkh2(v.z, v.w);
            *reinterpret_cast<uint2*>(Wu + nl * 8 + k4 * 2) = h;
        }
        // stage X: 128b x 16k fp32 -> fp16 (512 float4, 2 per thread)
#pragma unroll
        for (int r = 0; r < 2; ++r) {
            int e = t + r * 256;
            int b = e >> 2, k4 = e & 3;
            float4 v = *reinterpret_cast<const float4*>(
                X + ((size_t)b * NI + i) * DI + k4 * 4);
            uint2 h; h.x = pkh2(v.x, v.y); h.y = pkh2(v.z, v.w);
            *reinterpret_cast<uint2*>(Xu + b * 8 + k4 * 2) = h;
        }
        __syncthreads();

        // A fragments: 8 m-tiles
        unsigned a[8][4];
#pragma unroll
        for (int mt = 0; mt < 8; ++mt) {
            int base = (mt * 16 + g) * 8 + tq;   // uint index into Xu
            a[mt][0] = Xu[base];        // (g,    k 2t..2t+1)
            a[mt][1] = Xu[base + 64];   // (g+8,  k 2t..2t+1)
            a[mt][2] = Xu[base + 4];    // (g,    k 2t+8..9)
            a[mt][3] = Xu[base + 68];   // (g+8,  k 2t+8..9)
        }
        // B fragments: this warp's 2 n-tiles
        unsigned bf[2][2];
#pragma unroll
        for (int nt = 0; nt < 2; ++nt) {
            int base = (w * 16 + nt * 8 + g) * 8 + tq;
            bf[nt][0] = Wu[base];       // (k 2t..2t+1,  n g)
            bf[nt][1] = Wu[base + 4];   // (k 2t+8..9,   n g)
        }

#pragma unroll
        for (int nt = 0; nt < 2; ++nt) {
            const int n = nbase + w * 16 + nt * 8 + tq * 2;
#pragma unroll
            for (int mt = 0; mt < 8; ++mt) {
                float d0, d1, d2, d3;
                mma16816(d0, d1, d2, d3,
                         a[mt][0], a[mt][1], a[mt][2], a[mt][3],
                         bf[nt][0], bf[nt][1]);
                float* s = s0[nt * 8 + mt];
                s[0] += d0; s[1] += d1; s[2] += d2; s[3] += d3;
                const int bq = mt * 16 + g;
                __half2 h01 = __floats2half2_rn(d0, d1);
                __half2 h23 = __floats2half2_rn(d2, d3);
                *reinterpret_cast<__half2*>(
                    &g_Xhat[((size_t)bq * NI + i) * JD + n]) = h01;
                *reinterpret_cast<__half2*>(
                    &g_Xhat[((size_t)(bq + 8) * NI + i) * JD + n]) = h23;
            }
        }
    }

    // write S0 partials: [iblk][b][n]
    float* outp = g_S0part + (size_t)iblk * (NBATCH * JD);
#pragma unroll
    for (int nt = 0; nt < 2; ++nt) {
        const int n = nbase + w * 16 + nt * 8 + tq * 2;
#pragma unroll
        for (int mt = 0; mt < 8; ++mt) {
            const float* s = s0[nt * 8 + mt];
            const int bq = mt * 16 + g;
            *reinterpret_cast<float2*>(&outp[(size_t)bq * JD + n])
                = make_float2(s[0], s[1]);
            *reinterpret_cast<float2*>(&outp[(size_t)(bq + 8) * JD + n])
                = make_float2(s[2], s[3]);
        }
    }
}

// ---------------------------------------------------------------------------
// K2: reduce S0 partials + squash -> g_V0.  One thread per (b, j, d) = 65536.
// ---------------------------------------------------------------------------
__global__ void caps_squash_v0()
{
    int t = blockIdx.x * blockDim.x + threadIdx.x;
    float s = 0.f;
#pragma unroll 4
    for (int c = 0; c < NIB; ++c)
        s += g_S0part[(size_t)c * (NBATCH * JD) + t];
    s *= (1.0f / NO);
    float n2 = s * s;
#pragma unroll
    for (int off = 1; off < 16; off <<= 1)
        n2 += __shfl_xor_sync(0xffffffffu, n2, off);
    float f = sqrtf(n2) / (1.0f + n2);
    g_V0[t] = s * f;
}

// ---------------------------------------------------------------------------
// K3: warp per (b, i-chunk). lane = j. v0 and s1 in registers.
// Streams X_hat once (268 MB), one softmax per (b,i).
// ---------------------------------------------------------------------------
__global__ __launch_bounds__(256, 4)
void caps_route_s1()
{
    const int wid = blockIdx.x * 8 + (threadIdx.x >> 5);  // 0..4095
    const int j   = threadIdx.x & 31;
    const int b   = wid >> 5;          // 0..127
    const int ch  = wid & (WPB - 1);   // 0..31

    // v0[b][j][0..15] into registers
    float v[16];
    {
        const float4* vp = reinterpret_cast<const float4*>(
            &g_V0[((size_t)b * NO + j) * DO]);
#pragma unroll
        for (int q = 0; q < 4; ++q) {
            float4 x = vp[q];
            v[q*4+0] = x.x; v[q*4+1] = x.y; v[q*4+2] = x.z; v[q*4+3] = x.w;
        }
    }

    float s1[16];
#pragma unroll
    for (int d = 0; d < 16; ++d) s1[d] = 0.f;

    for (int iiv = 0; iiv < ICH3; ++iiv) {
        const int i = ch * ICH3 + iiv;
        const uint4* xp = reinterpret_cast<const uint4*>(
            &g_Xhat[((size_t)b * NI + i) * JD + j * DO]);
        uint4 x0 = xp[0], x1 = xp[1];

        float xf[16];
        {
            const unsigned u[8] = {x0.x, x0.y, x0.z, x0.w, x1.x, x1.y, x1.z, x1.w};
#pragma unroll
            for (int q = 0; q < 8; ++q) {
                float2 f2 = __half22float2(*reinterpret_cast<const __half2*>(&u[q]));
                xf[q*2+0] = f2.x; xf[q*2+1] = f2.y;
            }
        }

        // b1 logit for (b, i, j=lane)
        float p = 0.f;
#pragma unroll
        for (int d = 0; d < 16; ++d) p = fmaf(xf[d], v[d], p);

        // softmax over the 32 lanes (j axis)
        float m = p;
#pragma unroll
        for (int off = 16; off; off >>= 1)
            m = fmaxf(m, __shfl_xor_sync(0xffffffffu, m, off));
        float e = __expf(p - m);
        float ss = e;
#pragma unroll
        for (int off = 16; off; off >>= 1)
            ss += __shfl_xor_sync(0xffffffffu, ss, off);
        float c = e / ss;

#pragma unroll
        for (int d = 0; d < 16; ++d) s1[d] = fmaf(c, xf[d], s1[d]);
    }

    // store partials [ch][b][j][d]
    float* o = g_S1part + (((size_t)ch * NBATCH + b) * NO + j) * DO;
#pragma unroll
    for (int q = 0; q < 4; ++q)
        *reinterpret_cast<float4*>(o + q * 4)
            = make_float4(s1[q*4+0], s1[q*4+1], s1[q*4+2], s1[q*4+3]);
}

// ---------------------------------------------------------------------------
// K4: reduce S1 partials + squash -> output. One thread per (b, j, d).
// ---------------------------------------------------------------------------
__global__ void caps_squash_out(float* __restrict__ out)
{
    int t = blockIdx.x * blockDim.x + threadIdx.x;
    float s = 0.f;
#pragma unroll 4
    for (int c = 0; c < NCH1; ++c)
        s += g_S1part[(size_t)c * (NBATCH * JD) + t];
    float n2 = s * s;
#pragma unroll
    for (int off = 1; off < 16; off <<= 1)
        n2 += __shfl_xor_sync(0xffffffffu, n2, off);
    float f = sqrtf(n2) / (1.0f + n2);
    out[t] = s * f;
}

// ---------------------------------------------------------------------------
extern "C" void kernel_launch(void* const* d_in, const int* in_sizes, int n_in,
                              void* d_out, int out_size)
{
    const float* X = (const float*)d_in[0];
    const float* W = (const float*)d_in[1];
    // defensive: identify by size (X = 4,194,304 ; W = 16,777,216)
    if (n_in >= 2 && in_sizes[0] == NI * NO * DO * DI && in_sizes[1] == NBATCH * NI * DI) {
        W = (const float*)d_in[0];
        X = (const float*)d_in[1];
    }

    dim3 grid1(4, NIB);        // 1024 CTAs, 2/SM
    caps_xhat_s0_mma<<<grid1, 256>>>(X, W);
    caps_squash_v0<<<256, 256>>>();
    caps_route_s1<<<512, 256>>>();
    caps_squash_out<<<256, 256>>>((float*)d_out);
}

// round 8
// speedup vs baseline: 4.3485x; 1.6393x over previous
#include <cuda_runtime.h>
#include <cuda_fp16.h>
#include <math.h>

// Problem dims (fixed by the dataset)
#define NBATCH 128
#define NI     2048
#define DI     16
#define NO     32
#define DO     16
#define JD     (NO * DO)          // 512

// K1 (mma) tiling: CTA = 128 b x 128 n (quarter of W) x II i's
#define II     16
#define NIB    (NI / II)          // 128 i-blocks
// K3 tiling: warp per (b, i-chunk)
#define WPB    32                 // warps (i-chunks) per batch
#define ICH3   (NI / WPB)         // 64 i per warp
#define NCH1   WPB                // 32 S1 partial chunks

// Osm row stride in halves (128 data + 8 pad -> 272B rows, 4-bank shift/row)
#define OSTRIDE 136

// Deterministic buffers (no atomics anywhere).
// Xhat layout: [i][b][n] -- per-i tile contiguous (128 b x 512 n)
__device__ __half g_Xhat[(size_t)NI * NBATCH * JD];          // 268 MB fp16
__device__ float  g_S0part[(size_t)NIB * NBATCH * JD];       // 33.5 MB
__device__ float  g_S1part[(size_t)NCH1 * NBATCH * JD];      // 8.4 MB
__device__ float  g_V0[NBATCH * JD];

// ---------------------------------------------------------------------------
// mma.sync m16n8k16 f16 -> f32
// ---------------------------------------------------------------------------
__device__ __forceinline__ void mma16816(float& d0, float& d1, float& d2, float& d3,
                                         unsigned a0, unsigned a1, unsigned a2, unsigned a3,
                                         unsigned b0, unsigned b1)
{
    asm volatile(
        "mma.sync.aligned.m16n8k16.row.col.f32.f16.f16.f32 "
        "{%0,%1,%2,%3}, {%4,%5,%6,%7}, {%8,%9}, {%10,%11,%12,%13};"
        : "=f"(d0), "=f"(d1), "=f"(d2), "=f"(d3)
        : "r"(a0), "r"(a1), "r"(a2), "r"(a3), "r"(b0), "r"(b1),
          "f"(0.0f), "f"(0.0f), "f"(0.0f), "f"(0.0f));
}

__device__ __forceinline__ unsigned pkh2(float x, float y) {
    __half2 h = __floats2half2_rn(x, y);
    return *reinterpret_cast<unsigned*>(&h);
}

// ---------------------------------------------------------------------------
// K1: X_hat (fp16, [i][b][n]) + S0 partials via tensor cores.
// grid (4 nq, NIB), block 256 (8 warps), 2 CTAs/SM.
// Warp w covers n-local [16w, 16w+16), all 8 m-tiles (128 b).
// Output staged through smem for coalesced STG.128.
// ---------------------------------------------------------------------------
__global__ __launch_bounds__(256, 2)
void caps_xhat_s0_mma(const float* __restrict__ X, const float* __restrict__ W)
{
    __shared__ __align__(16) __half Wsm[128 * 16];        // 4 KB  [nlocal][k]
    __shared__ __align__(16) __half Xsm[128 * 16];        // 4 KB  [b][k]
    __shared__ __align__(16) __half Osm[128 * OSTRIDE];   // 34 KB [b][n+pad]

    const int nq    = blockIdx.x;
    const int iblk  = blockIdx.y;
    const int t     = threadIdx.x;
    const int w     = t >> 5;
    const int l     = t & 31;
    const int g     = l >> 2;       // fragment group (row)
    const int tq    = l & 3;        // fragment thread-in-group (col pair)
    const int nbase = nq * 128;

    unsigned* Wu = reinterpret_cast<unsigned*>(Wsm);
    unsigned* Xu = reinterpret_cast<unsigned*>(Xsm);

    float s0[16][4];                // [nt*8+mt][frag reg]
#pragma unroll
    for (int q = 0; q < 16; ++q) { s0[q][0]=0.f; s0[q][1]=0.f; s0[q][2]=0.f; s0[q][3]=0.f; }

    for (int ii = 0; ii < II; ++ii) {
        const int i = iblk * II + ii;
        __syncthreads();   // Osm readout of prev iter done; Wsm/Xsm free
        // stage W quarter: 128n x 16k fp32 -> fp16 (512 float4, 2 per thread)
#pragma unroll
        for (int r = 0; r < 2; ++r) {
            int e  = t + r * 256;
            int nl = e >> 2, k4 = e & 3;
            float4 v = *reinterpret_cast<const float4*>(
                W + ((size_t)i * JD + nbase + nl) * DI + k4 * 4);
            uint2 h; h.x = pkh2(v.x, v.y); h.y = pkh2(v.z, v.w);
            *reinterpret_cast<uint2*>(Wu + nl * 8 + k4 * 2) = h;
        }
        // stage X: 128b x 16k fp32 -> fp16 (512 float4, 2 per thread)
#pragma unroll
        for (int r = 0; r < 2; ++r) {
            int e = t + r * 256;
            int b = e >> 2, k4 = e & 3;
            float4 v = *reinterpret_cast<const float4*>(
                X + ((size_t)b * NI + i) * DI + k4 * 4);
            uint2 h; h.x = pkh2(v.x, v.y); h.y = pkh2(v.z, v.w);
            *reinterpret_cast<uint2*>(Xu + b * 8 + k4 * 2) = h;
        }
        __syncthreads();

        // A fragments: 8 m-tiles
        unsigned a[8][4];
#pragma unroll
        for (int mt = 0; mt < 8; ++mt) {
            int base = (mt * 16 + g) * 8 + tq;
            a[mt][0] = Xu[base];
            a[mt][1] = Xu[base + 64];
            a[mt][2] = Xu[base + 4];
            a[mt][3] = Xu[base + 68];
        }
        // B fragments: this warp's 2 n-tiles
        unsigned bf[2][2];
#pragma unroll
        for (int nt = 0; nt < 2; ++nt) {
            int base = (w * 16 + nt * 8 + g) * 8 + tq;
            bf[nt][0] = Wu[base];
            bf[nt][1] = Wu[base + 4];
        }

#pragma unroll
        for (int nt = 0; nt < 2; ++nt) {
            const int nl = w * 16 + nt * 8 + tq * 2;   // n-local
#pragma unroll
            for (int mt = 0; mt < 8; ++mt) {
                float d0, d1, d2, d3;
                mma16816(d0, d1, d2, d3,
                         a[mt][0], a[mt][1], a[mt][2], a[mt][3],
                         bf[nt][0], bf[nt][1]);
                float* s = s0[nt * 8 + mt];
                s[0] += d0; s[1] += d1; s[2] += d2; s[3] += d3;
                const int bq = mt * 16 + g;
                // STS.32, conflict-free: bank = (4g + const + tq) mod 32
                *reinterpret_cast<unsigned*>(&Osm[bq * OSTRIDE + nl])
                    = pkh2(d0, d1);
                *reinterpret_cast<unsigned*>(&Osm[(bq + 8) * OSTRIDE + nl])
                    = pkh2(d2, d3);
            }
        }
        __syncthreads();

        // coalesced write-out: 2048 16B-chunks, 8 per thread.
        // chunk e: b = e>>4, c16 = e&15. Warp covers 2 b-rows => 4 lines/instr.
        __half* xg = &g_Xhat[((size_t)i * NBATCH) * JD + nbase];
#pragma unroll
        for (int r = 0; r < 8; ++r) {
            int e  = t + r * 256;
            int b  = e >> 4, c16 = e & 15;
            uint4 v = *reinterpret_cast<const uint4*>(&Osm[b * OSTRIDE + c16 * 8]);
            *reinterpret_cast<uint4*>(&xg[(size_t)b * JD + c16 * 8]) = v;
        }
    }

    // write S0 partials: [iblk][b][n] (amortized over II=16 i's)
    float* outp = g_S0part + (size_t)iblk * (NBATCH * JD);
#pragma unroll
    for (int nt = 0; nt < 2; ++nt) {
        const int n = nbase + w * 16 + nt * 8 + tq * 2;
#pragma unroll
        for (int mt = 0; mt < 8; ++mt) {
            const float* s = s0[nt * 8 + mt];
            const int bq = mt * 16 + g;
            *reinterpret_cast<float2*>(&outp[(size_t)bq * JD + n])
                = make_float2(s[0], s[1]);
            *reinterpret_cast<float2*>(&outp[(size_t)(bq + 8) * JD + n])
                = make_float2(s[2], s[3]);
        }
    }
}

// ---------------------------------------------------------------------------
// K2: reduce S0 partials + squash -> g_V0.  One thread per (b, j, d) = 65536.
// ---------------------------------------------------------------------------
__global__ void caps_squash_v0()
{
    int t = blockIdx.x * blockDim.x + threadIdx.x;
    float s = 0.f;
#pragma unroll 4
    for (int c = 0; c < NIB; ++c)
        s += g_S0part[(size_t)c * (NBATCH * JD) + t];
    s *= (1.0f / NO);
    float n2 = s * s;
#pragma unroll
    for (int off = 1; off < 16; off <<= 1)
        n2 += __shfl_xor_sync(0xffffffffu, n2, off);
    float f = sqrtf(n2) / (1.0f + n2);
    g_V0[t] = s * f;
}

// ---------------------------------------------------------------------------
// K3: warp per (b, i-chunk). lane = j. v0 and s1 in registers.
// Streams X_hat ([i][b][n]) once, one softmax per (b,i). Unroll 2 i's.
// ---------------------------------------------------------------------------
__global__ __launch_bounds__(256, 4)
void caps_route_s1()
{
    const int wid = blockIdx.x * 8 + (threadIdx.x >> 5);  // 0..4095
    const int j   = threadIdx.x & 31;
    const int b   = wid >> 5;          // 0..127
    const int ch  = wid & (WPB - 1);   // 0..31

    // v0[b][j][0..15] into registers
    float v[16];
    {
        const float4* vp = reinterpret_cast<const float4*>(
            &g_V0[((size_t)b * NO + j) * DO]);
#pragma unroll
        for (int q = 0; q < 4; ++q) {
            float4 x = vp[q];
            v[q*4+0] = x.x; v[q*4+1] = x.y; v[q*4+2] = x.z; v[q*4+3] = x.w;
        }
    }

    float s1[16];
#pragma unroll
    for (int d = 0; d < 16; ++d) s1[d] = 0.f;

    for (int iiv = 0; iiv < ICH3; iiv += 2) {
        const int i0 = ch * ICH3 + iiv;

        uint4 xr[2][2];
#pragma unroll
        for (int u = 0; u < 2; ++u) {
            const uint4* xp = reinterpret_cast<const uint4*>(
                &g_Xhat[((size_t)(i0 + u) * NBATCH + b) * JD + j * DO]);
            xr[u][0] = xp[0]; xr[u][1] = xp[1];
        }

#pragma unroll
        for (int u = 0; u < 2; ++u) {
            float xf[16];
            {
                const unsigned uu[8] = {xr[u][0].x, xr[u][0].y, xr[u][0].z, xr[u][0].w,
                                        xr[u][1].x, xr[u][1].y, xr[u][1].z, xr[u][1].w};
#pragma unroll
                for (int q = 0; q < 8; ++q) {
                    float2 f2 = __half22float2(*reinterpret_cast<const __half2*>(&uu[q]));
                    xf[q*2+0] = f2.x; xf[q*2+1] = f2.y;
                }
            }

            float p = 0.f;
#pragma unroll
            for (int d = 0; d < 16; ++d) p = fmaf(xf[d], v[d], p);

            float m = p;
#pragma unroll
            for (int off = 16; off; off >>= 1)
                m = fmaxf(m, __shfl_xor_sync(0xffffffffu, m, off));
            float e = __expf(p - m);
            float ss = e;
#pragma unroll
            for (int off = 16; off; off >>= 1)
                ss += __shfl_xor_sync(0xffffffffu, ss, off);
            float c = e / ss;

#pragma unroll
            for (int d = 0; d < 16; ++d) s1[d] = fmaf(c, xf[d], s1[d]);
        }
    }

    // store partials [ch][b][j][d]
    float* o = g_S1part + (((size_t)ch * NBATCH + b) * NO + j) * DO;
#pragma unroll
    for (int q = 0; q < 4; ++q)
        *reinterpret_cast<float4*>(o + q * 4)
            = make_float4(s1[q*4+0], s1[q*4+1], s1[q*4+2], s1[q*4+3]);
}

// ---------------------------------------------------------------------------
// K4: reduce S1 partials + squash -> output. One thread per (b, j, d).
// ---------------------------------------------------------------------------
__global__ void caps_squash_out(float* __restrict__ out)
{
    int t = blockIdx.x * blockDim.x + threadIdx.x;
    float s = 0.f;
#pragma unroll 4
    for (int c = 0; c < NCH1; ++c)
        s += g_S1part[(size_t)c * (NBATCH * JD) + t];
    float n2 = s * s;
#pragma unroll
    for (int off = 1; off < 16; off <<= 1)
        n2 += __shfl_xor_sync(0xffffffffu, n2, off);
    float f = sqrtf(n2) / (1.0f + n2);
    out[t] = s * f;
}

// ---------------------------------------------------------------------------
extern "C" void kernel_launch(void* const* d_in, const int* in_sizes, int n_in,
                              void* d_out, int out_size)
{
    const float* X = (const float*)d_in[0];
    const float* W = (const float*)d_in[1];
    // defensive: identify by size (X = 4,194,304 ; W = 16,777,216)
    if (n_in >= 2 && in_sizes[0] == NI * NO * DO * DI && in_sizes[1] == NBATCH * NI * DI) {
        W = (const float*)d_in[0];
        X = (const float*)d_in[1];
    }

    dim3 grid1(4, NIB);        // 512 CTAs, 2/SM
    caps_xhat_s0_mma<<<grid1, 256>>>(X, W);
    caps_squash_v0<<<256, 256>>>();
    caps_route_s1<<<512, 256>>>();
    caps_squash_out<<<256, 256>>>((float*)d_out);
}